// round 10
// baseline (speedup 1.0000x reference)
#include <cuda_runtime.h>
#include <cuda_bf16.h>

// GRU scan: B=2048 sequences, T=2048 steps, D=3 input, H=32 hidden.
// out[b, t] = h[0] after step t.
//
// R10: in-warp ILP instead of cross-warp occupancy.
//  - 512 single-warp CTAs (4 CTAs/SM -> 1 warp per SMSP, ~500-reg budget).
//  - Each warp runs FOUR batches. Weights k-pair packed as f32x2:
//    48 u64 = 96 regs SHARED by all 4 batches (no duplication, no smem
//    weight reads -- R9's lane-strided smem table was the crossbar binder).
//  - Matvec = 192 fma.rn.f32x2/step in 12 independent chains -> a single
//    warp sustains the fma pipe at rt2; 4 independent activation chains
//    overlap the step-boundary latency.
//  - h exchange per batch via per-CTA smem broadcast (LDS.128, N=1),
//    double-buffered, one __syncwarp per step.
//  - EX2/RCP activations (tanh.approx is an fma-pipe polyfill on sm_103a).

#define T_DIM 2048
#define B_DIM 2048

typedef unsigned long long u64;

__device__ __forceinline__ u64 fma2(u64 a, u64 b, u64 c) {
    u64 d;
    asm("fma.rn.f32x2 %0, %1, %2, %3;" : "=l"(d) : "l"(a), "l"(b), "l"(c));
    return d;
}

__device__ __forceinline__ float foldadd(u64 p) {
    float lo, hi;
    asm("mov.b64 {%0, %1}, %2;" : "=f"(lo), "=f"(hi) : "l"(p));
    return lo + hi;
}

__device__ __forceinline__ float sigm_f(float x) {
    return __fdividef(1.0f, 1.0f + __expf(-x));
}

__device__ __forceinline__ float tanh_f(float x) {
    return 1.0f - __fdividef(2.0f, __expf(2.0f * x) + 1.0f);
}

__global__ void __launch_bounds__(32, 4)
gru_scan_kernel(const float* __restrict__ inp,      // [B, T, 3]
                const float* __restrict__ wih,      // [96, 3]
                const float* __restrict__ whh,      // [96, 32]
                const float* __restrict__ bias,     // [96]
                const float* __restrict__ bias_n,   // [32]
                float* __restrict__ out)            // [B, T]
{
    const int lane = threadIdx.x & 31;
    const int b0   = blockIdx.x * 4;         // this warp's 4 batches

    // double-buffered per-batch h slabs; 16B-aligned for LDS.128 broadcast
    __shared__ __align__(16) float hbuf[2][4][32];

    // --- Whh rows for this lane as packed k-pairs, shared by all batches ---
    u64 wr[16], wz[16], wa[16];
    {
        const u64* r0 = reinterpret_cast<const u64*>(whh + (size_t)(lane) * 32);
        const u64* r1 = reinterpret_cast<const u64*>(whh + (size_t)(32 + lane) * 32);
        const u64* r2 = reinterpret_cast<const u64*>(whh + (size_t)(64 + lane) * 32);
#pragma unroll
        for (int i = 0; i < 16; ++i) { wr[i] = r0[i]; wz[i] = r1[i]; wa[i] = r2[i]; }
    }
    const float wir0 = wih[lane * 3 + 0], wir1 = wih[lane * 3 + 1], wir2 = wih[lane * 3 + 2];
    const float wiz0 = wih[(32 + lane) * 3 + 0], wiz1 = wih[(32 + lane) * 3 + 1], wiz2 = wih[(32 + lane) * 3 + 2];
    const float wia0 = wih[(64 + lane) * 3 + 0], wia1 = wih[(64 + lane) * 3 + 1], wia2 = wih[(64 + lane) * 3 + 2];
    const float bir = bias[lane], biz = bias[32 + lane];
    const float bia = bias[64 + lane] + bias_n[lane];   // bias_n folded

    const float* xp = inp + (size_t)b0 * T_DIM * 3;
    float*       op = out + (size_t)b0 * T_DIM;

    float h[4] = {0.f, 0.f, 0.f, 0.f};
    float x[4][3];
#pragma unroll
    for (int b = 0; b < 4; ++b) {
        const float* p = xp + (size_t)b * T_DIM * 3;
        x[b][0] = __ldg(p + 0); x[b][1] = __ldg(p + 1); x[b][2] = __ldg(p + 2);
    }

    for (int t = 0; t < T_DIM; ++t) {
        // input gates for all 4 batches (independent scalar chains)
        float ir[4], iz[4], ia[4];
#pragma unroll
        for (int b = 0; b < 4; ++b) {
            ir[b] = fmaf(wir2, x[b][2], fmaf(wir1, x[b][1], fmaf(wir0, x[b][0], bir)));
            iz[b] = fmaf(wiz2, x[b][2], fmaf(wiz1, x[b][1], fmaf(wiz0, x[b][0], biz)));
            ia[b] = fmaf(wia2, x[b][2], fmaf(wia1, x[b][1], fmaf(wia0, x[b][0], bia)));
        }
        {   // prefetch next x for all batches (clamped, branch-free)
            int tn = (t + 1 < T_DIM) ? (t + 1) : t;
#pragma unroll
            for (int b = 0; b < 4; ++b) {
                const float* p = xp + (size_t)b * T_DIM * 3 + (size_t)tn * 3;
                x[b][0] = __ldg(p + 0); x[b][1] = __ldg(p + 1); x[b][2] = __ldg(p + 2);
            }
        }

        // publish h for all batches; double-buffered slot, one syncwarp/step
        const int slot = t & 1;
#pragma unroll
        for (int b = 0; b < 4; ++b) hbuf[slot][b][lane] = h[b];
        __syncwarp();

        // matvec: 12 independent packed chains (4 batches x 3 gates)
        u64 ar[4] = {0,0,0,0}, az[4] = {0,0,0,0}, aa[4] = {0,0,0,0};
#pragma unroll
        for (int i = 0; i < 8; ++i) {
            ulonglong2 hv[4];
#pragma unroll
            for (int b = 0; b < 4; ++b)
                hv[b] = reinterpret_cast<const ulonglong2*>(&hbuf[slot][b][0])[i];
#pragma unroll
            for (int b = 0; b < 4; ++b) {
                ar[b] = fma2(wr[2 * i],     hv[b].x, ar[b]);
                az[b] = fma2(wz[2 * i],     hv[b].x, az[b]);
                aa[b] = fma2(wa[2 * i],     hv[b].x, aa[b]);
                ar[b] = fma2(wr[2 * i + 1], hv[b].y, ar[b]);
                az[b] = fma2(wz[2 * i + 1], hv[b].y, az[b]);
                aa[b] = fma2(wa[2 * i + 1], hv[b].y, aa[b]);
            }
        }

        // activations + state update, 4 independent chains
#pragma unroll
        for (int b = 0; b < 4; ++b) {
            float hr = foldadd(ar[b]);
            float hz = foldadd(az[b]);
            float ha = foldadd(aa[b]);
            float r = sigm_f(ir[b] + hr);
            float z = sigm_f(iz[b] + hz);
            float n = tanh_f(fmaf(r, ha, ia[b]));
            h[b] = fmaf(z, h[b] - n, n);    // (1-z)*n + z*h
        }

        if (lane == 0) {
#pragma unroll
            for (int b = 0; b < 4; ++b)
                op[(size_t)b * T_DIM + t] = h[b];
        }
    }
}

extern "C" void kernel_launch(void* const* d_in, const int* in_sizes, int n_in,
                              void* d_out, int out_size) {
    const float* inp    = (const float*)d_in[0];
    const float* wih    = (const float*)d_in[1];
    const float* whh    = (const float*)d_in[2];
    const float* bias   = (const float*)d_in[3];
    const float* bias_n = (const float*)d_in[4];
    float* out = (float*)d_out;

    // 4 batches per warp, ONE warp per CTA -> 512 CTAs, 4 CTAs/SM,
    // one warp per SMSP with a ~500-reg budget.
    gru_scan_kernel<<<B_DIM / 4, 32>>>(inp, wih, whh, bias, bias_n, out);
}

// round 11
// speedup vs baseline: 1.5073x; 1.5073x over previous
#include <cuda_runtime.h>
#include <cuda_bf16.h>

// GRU scan: B=2048 sequences, T=2048 steps, D=3 input, H=32 hidden.
// out[b, t] = h[0] after step t.
//
// R11 = R5's occupancy (1 batch/warp, 2048 warps, 3.46/SMSP, occ 4) with
// register demand engineered under the 128-reg cap so ptxas does NOT spill
// (R5 spilled at demand ~140; that was its entire deficit):
//  - Whh k-pair packed f32x2, NO duplication: 48 u64 = 96 regs.
//  - accumulators initialized with the input-gate value in the lo half
//    (fold lo+hi then yields the pre-activation directly; 3 adds deleted).
//  - no x-prefetch registers: x reloaded per step (L1-resident line, 4
//    warps/SMSP hide the rare miss).
//  - double-buffered smem h broadcast (LDS.128, N=1), one syncwarp/step.
//  - EX2/RCP activations (tanh.approx = fma-pipe polyfill on sm_103a).
// Cross-round model: fma-busy/SMSP/step is ~constant (~370); cyc/step is set
// by latency exposure, which falls with warps/SMSP (R10:1w=1326, R8:2w=770,
// target here 3.46w spill-free: ~520-600).

#define T_DIM 2048
#define B_DIM 2048

typedef unsigned long long u64;

__device__ __forceinline__ u64 fma2(u64 a, u64 b, u64 c) {
    u64 d;
    asm("fma.rn.f32x2 %0, %1, %2, %3;" : "=l"(d) : "l"(a), "l"(b), "l"(c));
    return d;
}

__device__ __forceinline__ u64 pack2(float a, float b) {
    u64 d;
    asm("mov.b64 %0, {%1, %2};" : "=l"(d) : "f"(a), "f"(b));
    return d;
}

__device__ __forceinline__ float foldadd(u64 p) {
    float lo, hi;
    asm("mov.b64 {%0, %1}, %2;" : "=f"(lo), "=f"(hi) : "l"(p));
    return lo + hi;
}

__device__ __forceinline__ float sigm_f(float x) {
    return __fdividef(1.0f, 1.0f + __expf(-x));
}

__device__ __forceinline__ float tanh_f(float x) {
    return 1.0f - __fdividef(2.0f, __expf(2.0f * x) + 1.0f);
}

__global__ void __launch_bounds__(128, 4)
gru_scan_kernel(const float* __restrict__ inp,      // [B, T, 3]
                const float* __restrict__ wih,      // [96, 3]
                const float* __restrict__ whh,      // [96, 32]
                const float* __restrict__ bias,     // [96]
                const float* __restrict__ bias_n,   // [32]
                float* __restrict__ out)            // [B, T]
{
    const int lane = threadIdx.x & 31;
    const int warp = threadIdx.x >> 5;
    const int b    = blockIdx.x * 4 + warp;

    // per-warp double-buffered h slab; 16B-aligned for LDS.128 broadcast
    __shared__ __align__(16) float hbuf[4][2][32];

    // --- Whh rows for this lane as packed k-pairs (96 regs, no dup) ---
    u64 wr[16], wz[16], wa[16];
    {
        const u64* r0 = reinterpret_cast<const u64*>(whh + (size_t)(lane) * 32);
        const u64* r1 = reinterpret_cast<const u64*>(whh + (size_t)(32 + lane) * 32);
        const u64* r2 = reinterpret_cast<const u64*>(whh + (size_t)(64 + lane) * 32);
#pragma unroll
        for (int i = 0; i < 16; ++i) { wr[i] = r0[i]; wz[i] = r1[i]; wa[i] = r2[i]; }
    }
    const float wir0 = wih[lane * 3 + 0], wir1 = wih[lane * 3 + 1], wir2 = wih[lane * 3 + 2];
    const float wiz0 = wih[(32 + lane) * 3 + 0], wiz1 = wih[(32 + lane) * 3 + 1], wiz2 = wih[(32 + lane) * 3 + 2];
    const float wia0 = wih[(64 + lane) * 3 + 0], wia1 = wih[(64 + lane) * 3 + 1], wia2 = wih[(64 + lane) * 3 + 2];
    const float bir = bias[lane], biz = bias[32 + lane];
    const float bia = bias[64 + lane] + bias_n[lane];   // bias_n folded

    const float* xp = inp + (size_t)b * T_DIM * 3;
    float*       op = out + (size_t)b * T_DIM;

    float h = 0.0f;

    for (int t = 0; t < T_DIM; ++t) {
        // x loaded in-loop (no prefetch registers); line is L1-resident for
        // ~10 consecutive steps, occ-4 hides the per-line miss.
        const float* xt = xp + (size_t)t * 3;
        float x0 = __ldg(xt + 0), x1 = __ldg(xt + 1), x2 = __ldg(xt + 2);

        float ir = fmaf(wir2, x2, fmaf(wir1, x1, fmaf(wir0, x0, bir)));
        float iz = fmaf(wiz2, x2, fmaf(wiz1, x1, fmaf(wiz0, x0, biz)));
        float ia = fmaf(wia2, x2, fmaf(wia1, x1, fmaf(wia0, x0, bia)));

        // publish h_j; double-buffered slot => one syncwarp per step
        const int slot = t & 1;
        hbuf[warp][slot][lane] = h;
        __syncwarp();

        // matvec, accumulators seeded with the input gate in the lo half:
        // fold(lo+hi) then yields the full pre-activation (ig + hg).
        u64 ar = pack2(ir, 0.0f);
        u64 az = pack2(iz, 0.0f);
        u64 aa = pack2(ia, 0.0f);
        const ulonglong2* hp =
            reinterpret_cast<const ulonglong2*>(&hbuf[warp][slot][0]);
#pragma unroll
        for (int i = 0; i < 8; ++i) {
            ulonglong2 hv = hp[i];          // broadcast: h[4i..4i+3] as 2 pairs
            ar = fma2(wr[2 * i],     hv.x, ar);
            az = fma2(wz[2 * i],     hv.x, az);
            aa = fma2(wa[2 * i],     hv.x, aa);
            ar = fma2(wr[2 * i + 1], hv.y, ar);
            az = fma2(wz[2 * i + 1], hv.y, az);
            aa = fma2(wa[2 * i + 1], hv.y, aa);
        }
        float rs = foldadd(ar);             // ir + hr
        float zs = foldadd(az);             // iz + hz
        float as_ = foldadd(aa);            // ia + ha  (r applies to hg part only!)

        // NOTE: n = tanh(ia + r*ha); as_ = ia + ha, so ha = as_ - ia.
        float r = sigm_f(rs);
        float z = sigm_f(zs);
        float n = tanh_f(fmaf(r, as_ - ia, ia));
        h = fmaf(z, h - n, n);              // (1-z)*n + z*h

        if (lane == 0) op[t] = h;
    }
}

extern "C" void kernel_launch(void* const* d_in, const int* in_sizes, int n_in,
                              void* d_out, int out_size) {
    const float* inp    = (const float*)d_in[0];
    const float* wih    = (const float*)d_in[1];
    const float* whh    = (const float*)d_in[2];
    const float* bias   = (const float*)d_in[3];
    const float* bias_n = (const float*)d_in[4];
    float* out = (float*)d_out;

    // 1 batch per warp, 4 warps per CTA -> 512 CTAs, 2048 warps, single wave.
    gru_scan_kernel<<<B_DIM / 4, 128>>>(inp, wih, whh, bias, bias_n, out);
}

// round 14
// speedup vs baseline: 1.6024x; 1.0631x over previous
#include <cuda_runtime.h>
#include <cuda_bf16.h>

// GRU scan: B=2048 sequences, T=2048 steps, D=3 input, H=32 hidden.
// out[b, t] = h[0] after step t.
//
// R12 = R11 (occ-4, 1 batch/warp, 2048 warps, k-pair-packed Whh in 96 regs)
// with the remaining ~12 registers of spill pressure removed:
//  - input-gate weights + biases live in a CTA-shared table (3 float4 per
//    lane), read per step as 3 lane-strided LDS.128 (12 wavefronts/step --
//    well under the crossbar budget; R9's failure was 32 wf/step).
//  - the table is DUPLICATED per parity slot and indexed by (t&1) so the
//    LDS address is loop-variant -> ptxas cannot hoist it back into
//    registers and recreate the spill.
//  - accumulators seeded with ig in the lo half (R11 trick, folds free).
//  - double-buffered smem h broadcast, one syncwarp/step; EX2/RCP
//    activations (tanh.approx = fma-pipe polyfill on sm_103a).
// Register demand ~121 < 128 -> occ 4 with NO spills (watch regs < 128).

#define T_DIM 2048
#define B_DIM 2048

typedef unsigned long long u64;

__device__ __forceinline__ u64 fma2(u64 a, u64 b, u64 c) {
    u64 d;
    asm("fma.rn.f32x2 %0, %1, %2, %3;" : "=l"(d) : "l"(a), "l"(b), "l"(c));
    return d;
}

__device__ __forceinline__ u64 pack2(float a, float b) {
    u64 d;
    asm("mov.b64 %0, {%1, %2};" : "=l"(d) : "f"(a), "f"(b));
    return d;
}

__device__ __forceinline__ float foldadd(u64 p) {
    float lo, hi;
    asm("mov.b64 {%0, %1}, %2;" : "=f"(lo), "=f"(hi) : "l"(p));
    return lo + hi;
}

__device__ __forceinline__ float sigm_f(float x) {
    return __fdividef(1.0f, 1.0f + __expf(-x));
}

__device__ __forceinline__ float tanh_f(float x) {
    return 1.0f - __fdividef(2.0f, __expf(2.0f * x) + 1.0f);
}

__global__ void __launch_bounds__(128, 4)
gru_scan_kernel(const float* __restrict__ inp,      // [B, T, 3]
                const float* __restrict__ wih,      // [96, 3]
                const float* __restrict__ whh,      // [96, 32]
                const float* __restrict__ bias,     // [96]
                const float* __restrict__ bias_n,   // [32]
                float* __restrict__ out)            // [B, T]
{
    const int lane = threadIdx.x & 31;
    const int warp = threadIdx.x >> 5;
    const int b    = blockIdx.x * 4 + warp;

    // per-warp double-buffered h slab; 16B-aligned for LDS.128 broadcast
    __shared__ __align__(16) float hbuf[4][2][32];
    // input-gate weight table: igw[slot][gate][lane] = (w0, w1, w2, bias).
    // Duplicated across the two parity slots so the in-loop read address
    // depends on t (anti-hoist; keeps these 12 scalars OUT of registers).
    __shared__ __align__(16) float4 igw[2][3][32];

    {
        const int tid = threadIdx.x;
        if (tid < 96) {
            const int g = tid >> 5;        // gate 0=r, 1=z, 2=a
            const int l = tid & 31;
            const int row = g * 32 + l;
            float bb = bias[row];
            if (g == 2) bb += bias_n[l];   // fold bias_n into a-gate bias
            float4 v = make_float4(wih[row * 3 + 0], wih[row * 3 + 1],
                                   wih[row * 3 + 2], bb);
            igw[0][g][l] = v;
            igw[1][g][l] = v;
        }
    }

    // --- Whh rows for this lane as packed k-pairs (96 regs, no dup) ---
    u64 wr[16], wz[16], wa[16];
    {
        const u64* r0 = reinterpret_cast<const u64*>(whh + (size_t)(lane) * 32);
        const u64* r1 = reinterpret_cast<const u64*>(whh + (size_t)(32 + lane) * 32);
        const u64* r2 = reinterpret_cast<const u64*>(whh + (size_t)(64 + lane) * 32);
#pragma unroll
        for (int i = 0; i < 16; ++i) { wr[i] = r0[i]; wz[i] = r1[i]; wa[i] = r2[i]; }
    }

    const float* xp = inp + (size_t)b * T_DIM * 3;
    float*       op = out + (size_t)b * T_DIM;

    float h = 0.0f;

    __syncthreads();   // igw ready

    for (int t = 0; t < T_DIM; ++t) {
        const int slot = t & 1;

        // x loaded in-loop (L1-resident line ~10 steps; occ-4 hides misses)
        const float* xt = xp + (size_t)t * 3;
        float x0 = __ldg(xt + 0), x1 = __ldg(xt + 1), x2 = __ldg(xt + 2);

        // input-gate weights from the slot-indexed shared table
        float4 gr = igw[slot][0][lane];
        float4 gz = igw[slot][1][lane];
        float4 ga = igw[slot][2][lane];
        float ir = fmaf(gr.z, x2, fmaf(gr.y, x1, fmaf(gr.x, x0, gr.w)));
        float iz = fmaf(gz.z, x2, fmaf(gz.y, x1, fmaf(gz.x, x0, gz.w)));
        float ia = fmaf(ga.z, x2, fmaf(ga.y, x1, fmaf(ga.x, x0, ga.w)));

        // publish h_j; double-buffered slot => one syncwarp per step
        hbuf[warp][slot][lane] = h;
        __syncwarp();

        // matvec, accumulators seeded with ig in the lo half
        u64 ar = pack2(ir, 0.0f);
        u64 az = pack2(iz, 0.0f);
        u64 aa = pack2(ia, 0.0f);
        const ulonglong2* hp =
            reinterpret_cast<const ulonglong2*>(&hbuf[warp][slot][0]);
#pragma unroll
        for (int i = 0; i < 8; ++i) {
            ulonglong2 hv = hp[i];          // broadcast: h[4i..4i+3] as 2 pairs
            ar = fma2(wr[2 * i],     hv.x, ar);
            az = fma2(wz[2 * i],     hv.x, az);
            aa = fma2(wa[2 * i],     hv.x, aa);
            ar = fma2(wr[2 * i + 1], hv.y, ar);
            az = fma2(wz[2 * i + 1], hv.y, az);
            aa = fma2(wa[2 * i + 1], hv.y, aa);
        }
        float rs  = foldadd(ar);            // ir + hr
        float zs  = foldadd(az);            // iz + hz
        float as_ = foldadd(aa);            // ia + ha

        // n = tanh(ia + r*ha); ha = as_ - ia
        float r = sigm_f(rs);
        float z = sigm_f(zs);
        float n = tanh_f(fmaf(r, as_ - ia, ia));
        h = fmaf(z, h - n, n);              // (1-z)*n + z*h

        if (lane == 0) op[t] = h;
    }
}

extern "C" void kernel_launch(void* const* d_in, const int* in_sizes, int n_in,
                              void* d_out, int out_size) {
    const float* inp    = (const float*)d_in[0];
    const float* wih    = (const float*)d_in[1];
    const float* whh    = (const float*)d_in[2];
    const float* bias   = (const float*)d_in[3];
    const float* bias_n = (const float*)d_in[4];
    float* out = (float*)d_out;

    // 1 batch per warp, 4 warps per CTA -> 512 CTAs, 2048 warps, single wave.
    gru_scan_kernel<<<B_DIM / 4, 128>>>(inp, wih, whh, bias, bias_n, out);
}